// round 11
// baseline (speedup 1.0000x reference)
#include <cuda_runtime.h>
#include <cuda_bf16.h>
#include <mma.h>
#include <cstdint>

using namespace nvcuda;
typedef __nv_bfloat16 bf16;

// ---------------- scratch (device globals; no allocation) ---------------------
__device__ bf16  g_xnh[2*1024*1024], g_xnl[2*1024*1024];
__device__ bf16  g_wh [1152*1024],   g_wl [1152*1024];     // combined wq+wkv split
__device__ bf16  g_woh[1024*1024],   g_wol[1024*1024];
__device__ bf16  g_qh [2*16*1024*64],g_ql [2*16*1024*64];
__device__ bf16  g_kh [2*1024*64],   g_kl [2*1024*64];
__device__ bf16  g_vh [2*1024*64],   g_vl [2*1024*64];
__device__ float g_nk [64], g_nv[64];
__device__ bf16  g_oh [2*1024*1024], g_ol [2*1024*1024];
__device__ float g_y  [2*1024*1024];

// ---------------- cp.async helpers --------------------------------------------
__device__ __forceinline__ void cp_async16(void* smem, const void* gmem) {
    uint32_t s = (uint32_t)__cvta_generic_to_shared(smem);
    asm volatile("cp.async.cg.shared.global [%0], [%1], 16;\n" :: "r"(s), "l"(gmem));
}
__device__ __forceinline__ void cp_async4(void* smem, const void* gmem) {
    uint32_t s = (uint32_t)__cvta_generic_to_shared(smem);
    asm volatile("cp.async.ca.shared.global [%0], [%1], 4;\n" :: "r"(s), "l"(gmem));
}
#define CP_COMMIT() asm volatile("cp.async.commit_group;\n" ::)
#define CP_WAIT(N)  asm volatile("cp.async.wait_group %0;\n" :: "n"(N))

__device__ __forceinline__ void split_store(float v, bf16* hp, bf16* lp) {
    bf16 h = __float2bfloat16(v);
    *hp = h;
    *lp = __float2bfloat16(v - __bfloat162float(h));
}

// ---------------- LayerNorm (final, f32 out) -----------------------------------
__global__ __launch_bounds__(256) void ln_kernel(const float* __restrict__ x,
                                                 const float* __restrict__ g,
                                                 float* __restrict__ out) {
    const int row = blockIdx.x;
    const int tid = threadIdx.x;
    float4 a = ((const float4*)(x + (size_t)row * 1024))[tid];
    float s = a.x + a.y + a.z + a.w;
    float q = a.x * a.x + a.y * a.y + a.z * a.z + a.w * a.w;
    #pragma unroll
    for (int o = 16; o > 0; o >>= 1) {
        s += __shfl_xor_sync(0xffffffffu, s, o);
        q += __shfl_xor_sync(0xffffffffu, q, o);
    }
    __shared__ float ss[8], qq[8];
    if ((tid & 31) == 0) { ss[tid >> 5] = s; qq[tid >> 5] = q; }
    __syncthreads();
    if (tid < 32) {
        float s2 = (tid < 8) ? ss[tid] : 0.f;
        float q2 = (tid < 8) ? qq[tid] : 0.f;
        #pragma unroll
        for (int o = 4; o > 0; o >>= 1) {
            s2 += __shfl_xor_sync(0xffffffffu, s2, o);
            q2 += __shfl_xor_sync(0xffffffffu, q2, o);
        }
        if (tid == 0) { ss[0] = s2; qq[0] = q2; }
    }
    __syncthreads();
    const float mean = ss[0] * (1.f / 1024.f);
    const float var  = qq[0] * (1.f / 1024.f) - mean * mean;
    const float rstd = rsqrtf(var + 1e-5f);
    float4 gv = ((const float4*)g)[tid];
    float4 o4;
    o4.x = (a.x - mean) * rstd * gv.x;
    o4.y = (a.y - mean) * rstd * gv.y;
    o4.z = (a.z - mean) * rstd * gv.z;
    o4.w = (a.w - mean) * rstd * gv.w;
    ((float4*)(out + (size_t)row * 1024))[tid] = o4;
}

// ---------------- LayerNorm writing bf16 hi/lo directly (first LN) -------------
__global__ __launch_bounds__(256) void ln_split_kernel(const float* __restrict__ x,
                                                       const float* __restrict__ g,
                                                       bf16* __restrict__ oh,
                                                       bf16* __restrict__ ol) {
    const int row = blockIdx.x;
    const int tid = threadIdx.x;
    float4 a = ((const float4*)(x + (size_t)row * 1024))[tid];
    float s = a.x + a.y + a.z + a.w;
    float q = a.x * a.x + a.y * a.y + a.z * a.z + a.w * a.w;
    #pragma unroll
    for (int o = 16; o > 0; o >>= 1) {
        s += __shfl_xor_sync(0xffffffffu, s, o);
        q += __shfl_xor_sync(0xffffffffu, q, o);
    }
    __shared__ float ss[8], qq[8];
    if ((tid & 31) == 0) { ss[tid >> 5] = s; qq[tid >> 5] = q; }
    __syncthreads();
    if (tid < 32) {
        float s2 = (tid < 8) ? ss[tid] : 0.f;
        float q2 = (tid < 8) ? qq[tid] : 0.f;
        #pragma unroll
        for (int o = 4; o > 0; o >>= 1) {
            s2 += __shfl_xor_sync(0xffffffffu, s2, o);
            q2 += __shfl_xor_sync(0xffffffffu, q2, o);
        }
        if (tid == 0) { ss[0] = s2; qq[0] = q2; }
    }
    __syncthreads();
    const float mean = ss[0] * (1.f / 1024.f);
    const float var  = qq[0] * (1.f / 1024.f) - mean * mean;
    const float rstd = rsqrtf(var + 1e-5f);
    float4 gv = ((const float4*)g)[tid];
    float v0 = (a.x - mean) * rstd * gv.x;
    float v1 = (a.y - mean) * rstd * gv.y;
    float v2 = (a.z - mean) * rstd * gv.z;
    float v3 = (a.w - mean) * rstd * gv.w;
    size_t base = (size_t)row * 1024 + tid * 4;
    bf16 h0 = __float2bfloat16(v0), h1 = __float2bfloat16(v1);
    bf16 h2 = __float2bfloat16(v2), h3 = __float2bfloat16(v3);
    __nv_bfloat162* hp = (__nv_bfloat162*)(oh + base);
    __nv_bfloat162* lp = (__nv_bfloat162*)(ol + base);
    hp[0] = __halves2bfloat162(h0, h1); hp[1] = __halves2bfloat162(h2, h3);
    lp[0] = __halves2bfloat162(__float2bfloat16(v0 - __bfloat162float(h0)),
                               __float2bfloat16(v1 - __bfloat162float(h1)));
    lp[1] = __halves2bfloat162(__float2bfloat16(v2 - __bfloat162float(h2)),
                               __float2bfloat16(v3 - __bfloat162float(h3)));
}

// ---------------- all weight splits + null-kv prep in one launch ----------------
// blocks [0,1024): w_q -> g_wh/g_wl rows 0..1023
// blocks [1024,1152): w_kv -> g_wh/g_wl rows 1024..1151
// blocks [1152,2176): w_out -> g_woh/g_wol
// block 2176: null_kv prep
__global__ __launch_bounds__(256) void split_w_all(const float* __restrict__ wq,
                                                   const float* __restrict__ wkv,
                                                   const float* __restrict__ wout,
                                                   const float* __restrict__ null_kv) {
    const int bidx = blockIdx.x;
    const int tid = threadIdx.x;
    const float* src; bf16 *hi, *lo; int i;
    if (bidx < 1024) {
        i = bidx * 256 + tid; src = wq; hi = g_wh; lo = g_wl;
    } else if (bidx < 1152) {
        i = (bidx - 1024) * 256 + tid; src = wkv; hi = g_wh + 1024 * 1024; lo = g_wl + 1024 * 1024;
    } else if (bidx < 2176) {
        i = (bidx - 1152) * 256 + tid; src = wout; hi = g_woh; lo = g_wol;
    } else {
        const int lane = tid & 31;
        if (tid < 32) {
            float v0 = null_kv[lane], v1 = null_kv[lane + 32];
            float s = v0 * v0 + v1 * v1;
            #pragma unroll
            for (int o = 16; o > 0; o >>= 1) s += __shfl_xor_sync(0xffffffffu, s, o);
            float sc = 4.f / fmaxf(sqrtf(s), 1e-12f);
            g_nk[lane] = v0 * sc; g_nk[lane + 32] = v1 * sc;
        } else if (tid < 64) {
            g_nv[lane] = null_kv[64 + lane];
            g_nv[lane + 32] = null_kv[96 + lane];
        }
        return;
    }
    float4 v = ((const float4*)src)[i];
    bf16 h0 = __float2bfloat16(v.x), h1 = __float2bfloat16(v.y);
    bf16 h2 = __float2bfloat16(v.z), h3 = __float2bfloat16(v.w);
    __nv_bfloat162* hp = (__nv_bfloat162*)(hi + 4 * (size_t)i);
    __nv_bfloat162* lp = (__nv_bfloat162*)(lo + 4 * (size_t)i);
    hp[0] = __halves2bfloat162(h0, h1); hp[1] = __halves2bfloat162(h2, h3);
    lp[0] = __halves2bfloat162(__float2bfloat16(v.x - __bfloat162float(h0)),
                               __float2bfloat16(v.y - __bfloat162float(h1)));
    lp[1] = __halves2bfloat162(__float2bfloat16(v.z - __bfloat162float(h2)),
                               __float2bfloat16(v.w - __bfloat162float(h3)));
}

// ---------------- bf16x3 GEMM, cp.async double-buffered ------------------------
// MODE 0: qkv (A = xn split, B = combined w split); epilogue fuses l2norm + split
// MODE 1: out (A = o split,  B = wout split) -> g_y f32
#define GLDA 40
#define LDC  68

template<int MODE>
__global__ __launch_bounds__(256, 2) void gemm_kernel() {
    extern __shared__ char smraw[];
    bf16* Ah = (bf16*)smraw;
    bf16* Al = Ah + 2 * 128 * GLDA;
    bf16* Bh = Al + 2 * 128 * GLDA;
    bf16* Bl = Bh + 2 * 64 * GLDA;

    const int nbase = blockIdx.x * 64;
    const int m0    = blockIdx.y * 128;
    const bf16 *gAh, *gAl, *gBh, *gBl;
    if (MODE == 0) {
        gAh = g_xnh; gAl = g_xnl;
        gBh = g_wh + (size_t)nbase * 1024; gBl = g_wl + (size_t)nbase * 1024;
    } else {
        gAh = g_oh; gAl = g_ol;
        gBh = g_woh + (size_t)nbase * 1024; gBl = g_wol + (size_t)nbase * 1024;
    }
    const int tid = threadIdx.x;
    const int warp = tid >> 5;
    const int wr = warp >> 1, wc = warp & 1;

    wmma::fragment<wmma::accumulator, 16, 16, 16, float> c[2][2];
    #pragma unroll
    for (int i = 0; i < 2; i++)
        #pragma unroll
        for (int j = 0; j < 2; j++) wmma::fill_fragment(c[i][j], 0.f);

    auto load_stage = [&](int s, int k0) {
        bf16* ah = Ah + s * 128 * GLDA; bf16* al = Al + s * 128 * GLDA;
        bf16* bh = Bh + s * 64  * GLDA; bf16* bl = Bl + s * 64  * GLDA;
        #pragma unroll
        for (int idx = tid; idx < 512; idx += 256) {
            int r = idx >> 2, c8 = idx & 3;
            cp_async16(ah + r * GLDA + c8 * 8, gAh + (size_t)(m0 + r) * 1024 + k0 + c8 * 8);
            cp_async16(al + r * GLDA + c8 * 8, gAl + (size_t)(m0 + r) * 1024 + k0 + c8 * 8);
        }
        {
            int r = tid >> 2, c8 = tid & 3;
            cp_async16(bh + r * GLDA + c8 * 8, gBh + (size_t)r * 1024 + k0 + c8 * 8);
            cp_async16(bl + r * GLDA + c8 * 8, gBl + (size_t)r * 1024 + k0 + c8 * 8);
        }
    };

    load_stage(0, 0);
    CP_COMMIT();

    for (int i = 0; i < 32; i++) {
        if (i < 31) load_stage((i + 1) & 1, (i + 1) * 32);
        CP_COMMIT();
        CP_WAIT(1);
        __syncthreads();
        const int s = i & 1;
        bf16* ahp = Ah + s * 128 * GLDA; bf16* alp = Al + s * 128 * GLDA;
        bf16* bhp = Bh + s * 64  * GLDA; bf16* blp = Bl + s * 64  * GLDA;
        #pragma unroll
        for (int kk = 0; kk < 2; kk++) {
            wmma::fragment<wmma::matrix_a, 16, 16, 16, bf16, wmma::row_major> ah[2], al[2];
            wmma::fragment<wmma::matrix_b, 16, 16, 16, bf16, wmma::col_major> bh[2], bl[2];
            #pragma unroll
            for (int t = 0; t < 2; t++) {
                wmma::load_matrix_sync(ah[t], ahp + (wr * 32 + t * 16) * GLDA + kk * 16, GLDA);
                wmma::load_matrix_sync(al[t], alp + (wr * 32 + t * 16) * GLDA + kk * 16, GLDA);
                wmma::load_matrix_sync(bh[t], bhp + (wc * 32 + t * 16) * GLDA + kk * 16, GLDA);
                wmma::load_matrix_sync(bl[t], blp + (wc * 32 + t * 16) * GLDA + kk * 16, GLDA);
            }
            #pragma unroll
            for (int t = 0; t < 2; t++)
                #pragma unroll
                for (int j = 0; j < 2; j++) {
                    wmma::mma_sync(c[t][j], ah[t], bh[j], c[t][j]);
                    wmma::mma_sync(c[t][j], ah[t], bl[j], c[t][j]);
                    wmma::mma_sync(c[t][j], al[t], bh[j], c[t][j]);
                }
        }
        __syncthreads();
    }

    if (MODE == 1) {
        #pragma unroll
        for (int i = 0; i < 2; i++)
            #pragma unroll
            for (int j = 0; j < 2; j++)
                wmma::store_matrix_sync(g_y + (size_t)(m0 + wr * 32 + i * 16) * 1024 + nbase + wc * 32 + j * 16,
                                        c[i][j], 1024, wmma::mem_row_major);
        return;
    }

    // ---- MODE 0 epilogue: stage C, fused l2norm (q,k) / copy (v), split hi/lo --
    float* Cs = (float*)smraw;    // 128 x LDC f32 = 34816 B (smem reuse, post-sync)
    #pragma unroll
    for (int i = 0; i < 2; i++)
        #pragma unroll
        for (int j = 0; j < 2; j++)
            wmma::store_matrix_sync(Cs + (size_t)(wr * 32 + i * 16) * LDC + wc * 32 + j * 16,
                                    c[i][j], LDC, wmma::mem_row_major);
    __syncthreads();

    const int b  = m0 >> 10;
    const int i0 = m0 & 1023;
    if (nbase < 1024 + 64) {
        // q head (nbase<1024) or k (nbase==1024): l2norm rows * 4, split
        bf16 *dh, *dl;
        if (nbase < 1024) {
            const int h = nbase >> 6;
            dh = g_qh + ((size_t)(b * 16 + h) * 1024 + i0) * 64;
            dl = g_ql + ((size_t)(b * 16 + h) * 1024 + i0) * 64;
        } else {
            dh = g_kh + ((size_t)b * 1024 + i0) * 64;
            dl = g_kl + ((size_t)b * 1024 + i0) * 64;
        }
        const int r = tid >> 1, half = (tid & 1) * 32;
        float s = 0.f;
        #pragma unroll 8
        for (int cc = 0; cc < 32; cc++) {
            float v = Cs[r * LDC + half + cc];
            s += v * v;
        }
        s += __shfl_xor_sync(0xffffffffu, s, 1);
        const float sc = 4.f / fmaxf(sqrtf(s), 1e-12f);
        #pragma unroll 8
        for (int cc = 0; cc < 32; cc++) {
            float v = Cs[r * LDC + half + cc] * sc;
            split_store(v, dh + (size_t)r * 64 + half + cc, dl + (size_t)r * 64 + half + cc);
        }
    } else {
        // v: plain split copy
        bf16* dh = g_vh + ((size_t)b * 1024 + i0) * 64;
        bf16* dl = g_vl + ((size_t)b * 1024 + i0) * 64;
        for (int idx = tid; idx < 128 * 64; idx += 256) {
            int r = idx >> 6, cc = idx & 63;
            split_store(Cs[r * LDC + cc], dh + (size_t)r * 64 + cc, dl + (size_t)r * 64 + cc);
        }
    }
}

// ---------------- attention (bf16x3, cp.async pipelined) -----------------------
#define SB   72     // bf16 tile stride
#define LDS_ 68     // fp32 stride (S, bias)
#define ATTN_SMEM_BYTES (6*64*SB*2 + 2*64*LDS_*4 + 384*4)   // 91648

__global__ __launch_bounds__(256, 2) void attn_kernel(const float* __restrict__ bias) {
    extern __shared__ char smraw[];
    bf16*  PQh = (bf16*)smraw;          // Q (prologue) then P
    bf16*  PQl = PQh + 64 * SB;
    bf16*  Kh  = PQl + 64 * SB;
    bf16*  Kl  = Kh  + 64 * SB;
    bf16*  Vh  = Kl  + 64 * SB;
    bf16*  Vl  = Vh  + 64 * SB;
    float* Ss  = (float*)(Vl + 64 * SB);
    float* Bs  = Ss + 64 * LDS_;
    float* e0  = Bs + 64 * LDS_;
    float* den = e0 + 64;
    float* denp = den + 64;

    const int qt = blockIdx.x, bh = blockIdx.y;
    const int b = bh >> 4, h = bh & 15;
    const int i0 = qt * 64;
    const int tid = threadIdx.x;
    const int warp = tid >> 5;
    const int wr = warp >> 1, wc = warp & 1;

    const float* bias_p = bias + (size_t)bh * 1024 * 1025;
    const bf16* khb = g_kh + (size_t)b * 1024 * 64;
    const bf16* klb = g_kl + (size_t)b * 1024 * 64;
    const bf16* vhb = g_vh + (size_t)b * 1024 * 64;
    const bf16* vlb = g_vl + (size_t)b * 1024 * 64;
    const bf16* qhb = g_qh + ((size_t)(b * 16 + h) * 1024 + i0) * 64;
    const bf16* qlb = g_ql + ((size_t)(b * 16 + h) * 1024 + i0) * 64;

    // prologue: G1 = {Q, K0, V0},  G2 = {bias0}
    #pragma unroll
    for (int idx = tid; idx < 512; idx += 256) {
        int r = idx >> 3, c8 = idx & 7;
        cp_async16(PQh + r * SB + c8 * 8, qhb + (size_t)r * 64 + c8 * 8);
        cp_async16(PQl + r * SB + c8 * 8, qlb + (size_t)r * 64 + c8 * 8);
        cp_async16(Kh  + r * SB + c8 * 8, khb + (size_t)r * 64 + c8 * 8);
        cp_async16(Kl  + r * SB + c8 * 8, klb + (size_t)r * 64 + c8 * 8);
        cp_async16(Vh  + r * SB + c8 * 8, vhb + (size_t)r * 64 + c8 * 8);
        cp_async16(Vl  + r * SB + c8 * 8, vlb + (size_t)r * 64 + c8 * 8);
    }
    CP_COMMIT();
    #pragma unroll 4
    for (int idx = tid; idx < 4096; idx += 256) {
        int r = idx >> 6, c = idx & 63;
        cp_async4(Bs + r * LDS_ + c, bias_p + (size_t)(i0 + r) * 1025 + 1 + c);
    }
    CP_COMMIT();
    CP_WAIT(1);
    __syncthreads();

    // Q fragments -> registers (held for whole kernel)
    wmma::fragment<wmma::matrix_a, 16, 16, 16, bf16, wmma::row_major> qfh[4], qfl[4];
    #pragma unroll
    for (int kk = 0; kk < 4; kk++) {
        wmma::load_matrix_sync(qfh[kk], PQh + wr * 16 * SB + kk * 16, SB);
        wmma::load_matrix_sync(qfl[kk], PQl + wr * 16 * SB + kk * 16, SB);
    }

    // null-key column
    if (tid < 64) {
        float s = 0.f;
        #pragma unroll 8
        for (int d = 0; d < 64; d++)
            s += (__bfloat162float(PQh[tid * SB + d]) + __bfloat162float(PQl[tid * SB + d])) * g_nk[d];
        float e = __expf(s + bias_p[(size_t)(i0 + tid) * 1025]);
        e0[tid] = e;
        den[tid] = e;
    }
    __syncthreads();   // Q smem consumed; PQ may now become P

    wmma::fragment<wmma::accumulator, 16, 16, 16, float> of[2];
    wmma::fill_fragment(of[0], 0.f);
    wmma::fill_fragment(of[1], 0.f);

    for (int kt = 0; kt < 16; kt++) {
        // ---- S = Q K^T (bf16x3) ----
        wmma::fragment<wmma::accumulator, 16, 16, 16, float> sf[2];
        wmma::fill_fragment(sf[0], 0.f);
        wmma::fill_fragment(sf[1], 0.f);
        #pragma unroll
        for (int kk = 0; kk < 4; kk++) {
            #pragma unroll
            for (int j = 0; j < 2; j++) {
                wmma::fragment<wmma::matrix_b, 16, 16, 16, bf16, wmma::col_major> kbh, kbl;
                wmma::load_matrix_sync(kbh, Kh + (wc * 32 + j * 16) * SB + kk * 16, SB);
                wmma::load_matrix_sync(kbl, Kl + (wc * 32 + j * 16) * SB + kk * 16, SB);
                wmma::mma_sync(sf[j], qfh[kk], kbh, sf[j]);
                wmma::mma_sync(sf[j], qfh[kk], kbl, sf[j]);
                wmma::mma_sync(sf[j], qfl[kk], kbh, sf[j]);
            }
        }
        #pragma unroll
        for (int j = 0; j < 2; j++)
            wmma::store_matrix_sync(Ss + wr * 16 * LDS_ + wc * 32 + j * 16, sf[j], LDS_,
                                    wmma::mem_row_major);
        __syncthreads();                              // K consumed, S ready

        // issue K(kt+1)
        if (kt < 15) {
            int j0n = (kt + 1) * 64;
            #pragma unroll
            for (int idx = tid; idx < 512; idx += 256) {
                int r = idx >> 3, c8 = idx & 7;
                cp_async16(Kh + r * SB + c8 * 8, khb + (size_t)(j0n + r) * 64 + c8 * 8);
                cp_async16(Kl + r * SB + c8 * 8, klb + (size_t)(j0n + r) * 64 + c8 * 8);
            }
        }
        CP_COMMIT();
        CP_WAIT(1);                                   // drains bias(kt) (+V(kt) from prev iter)
        __syncthreads();

        // ---- P = exp(S + bias), split to bf16 hi/lo ----
        {
            const int r = tid >> 2, cb = (tid & 3) * 16;
            float local = 0.f;
            #pragma unroll
            for (int c = 0; c < 16; c++) {
                float p = __expf(Ss[r * LDS_ + cb + c] + Bs[r * LDS_ + cb + c]);
                local += p;
                bf16 ph = __float2bfloat16(p);
                PQh[r * SB + cb + c] = ph;
                PQl[r * SB + cb + c] = __float2bfloat16(p - __bfloat162float(ph));
            }
            denp[tid] = local;
        }
        __syncthreads();
        if (tid < 64)
            den[tid] += denp[4 * tid] + denp[4 * tid + 1] + denp[4 * tid + 2] + denp[4 * tid + 3];

        // ---- O += P V (bf16x3) ----
        #pragma unroll
        for (int kk = 0; kk < 4; kk++) {
            wmma::fragment<wmma::matrix_a, 16, 16, 16, bf16, wmma::row_major> pfh, pfl;
            wmma::load_matrix_sync(pfh, PQh + wr * 16 * SB + kk * 16, SB);
            wmma::load_matrix_sync(pfl, PQl + wr * 16 * SB + kk * 16, SB);
            #pragma unroll
            for (int j = 0; j < 2; j++) {
                wmma::fragment<wmma::matrix_b, 16, 16, 16, bf16, wmma::row_major> vbh, vbl;
                wmma::load_matrix_sync(vbh, Vh + kk * 16 * SB + wc * 32 + j * 16, SB);
                wmma::load_matrix_sync(vbl, Vl + kk * 16 * SB + wc * 32 + j * 16, SB);
                wmma::mma_sync(of[j], pfh, vbh, of[j]);
                wmma::mma_sync(of[j], pfh, vbl, of[j]);
                wmma::mma_sync(of[j], pfl, vbh, of[j]);
            }
        }
        __syncthreads();                              // V and P consumed

        // issue V(kt+1) and bias(kt+1)
        if (kt < 15) {
            int j0n = (kt + 1) * 64;
            #pragma unroll
            for (int idx = tid; idx < 512; idx += 256) {
                int r = idx >> 3, c8 = idx & 7;
                cp_async16(Vh + r * SB + c8 * 8, vhb + (size_t)(j0n + r) * 64 + c8 * 8);
                cp_async16(Vl + r * SB + c8 * 8, vlb + (size_t)(j0n + r) * 64 + c8 * 8);
            }
        }
        CP_COMMIT();
        if (kt < 15) {
            int j0n = (kt + 1) * 64;
            #pragma unroll 4
            for (int idx = tid; idx < 4096; idx += 256) {
                int r = idx >> 6, c = idx & 63;
                cp_async4(Bs + r * LDS_ + c, bias_p + (size_t)(i0 + r) * 1025 + 1 + j0n + c);
            }
        }
        CP_COMMIT();
        CP_WAIT(2);                                   // drains K(kt+1); leaves V,B in flight
        __syncthreads();
    }
    CP_WAIT(0);

    // epilogue: out = (O + e0*nv)/den, split to bf16 hi/lo, [b, i, h*64+d]
    #pragma unroll
    for (int j = 0; j < 2; j++)
        wmma::store_matrix_sync(Ss + wr * 16 * LDS_ + wc * 32 + j * 16, of[j], LDS_,
                                wmma::mem_row_major);
    __syncthreads();
    {
        const int r = tid >> 2, cb = (tid & 3) * 16;
        const float invd = 1.f / den[r];
        const float e = e0[r];
        const size_t obase = ((size_t)(b * 1024 + i0 + r)) * 1024 + h * 64 + cb;
        #pragma unroll
        for (int c = 0; c < 16; c++) {
            float ov = (Ss[r * LDS_ + cb + c] + e * g_nv[cb + c]) * invd;
            split_store(ov, g_oh + obase + c, g_ol + obase + c);
        }
    }
}

// ---------------- launch -------------------------------------------------------
extern "C" void kernel_launch(void* const* d_in, const int* in_sizes, int n_in,
                              void* d_out, int out_size) {
    const float* x       = (const float*)d_in[0];
    const float* bias    = (const float*)d_in[1];
    const float* g_in    = (const float*)d_in[2];
    const float* w_q     = (const float*)d_in[3];
    const float* w_kv    = (const float*)d_in[4];
    const float* null_kv = (const float*)d_in[5];
    const float* w_out   = (const float*)d_in[6];
    const float* g_out   = (const float*)d_in[7];
    float* out = (float*)d_out;

    float* y_p;
    bf16 *xnh_p, *xnl_p;
    cudaGetSymbolAddress((void**)&y_p,   g_y);
    cudaGetSymbolAddress((void**)&xnh_p, g_xnh);
    cudaGetSymbolAddress((void**)&xnl_p, g_xnl);

    const int GEMM_SMEM = (2 * 128 * GLDA + 2 * 128 * GLDA + 2 * 64 * GLDA + 2 * 64 * GLDA) * 2; // 61440
    cudaFuncSetAttribute(gemm_kernel<0>, cudaFuncAttributeMaxDynamicSharedMemorySize, GEMM_SMEM);
    cudaFuncSetAttribute(gemm_kernel<1>, cudaFuncAttributeMaxDynamicSharedMemorySize, GEMM_SMEM);
    cudaFuncSetAttribute(attn_kernel, cudaFuncAttributeMaxDynamicSharedMemorySize, ATTN_SMEM_BYTES);

    // 1. LN(x) -> split xn (hi/lo)
    ln_split_kernel<<<2048, 256>>>(x, g_in, xnh_p, xnl_p);
    // 2. all weight splits + null-kv prep
    split_w_all<<<2177, 256>>>(w_q, w_kv, w_out, null_kv);
    // 3. fused QKV GEMM (epilogue: l2norm + split q/k, split v)
    gemm_kernel<0><<<dim3(18, 16), 256, GEMM_SMEM>>>();
    // 4. attention (epilogue: split o)
    attn_kernel<<<dim3(16, 32), 256, ATTN_SMEM_BYTES>>>(bias);
    // 5. out projection -> g_y f32
    gemm_kernel<1><<<dim3(16, 16), 256, GEMM_SMEM>>>();
    // 6. final LN -> d_out
    ln_kernel<<<2048, 256>>>(y_p, g_out, out);
}